// round 1
// baseline (speedup 1.0000x reference)
#include <cuda_runtime.h>

#define HIDDEN 51
#define JP 64          // padded hidden units (threads per half)
#define KH 26          // k-iterations per half (2*26=52 covers 51 + 1 zero pad)
#define NB 8           // batch rows per block
#define CH 50          // x chunk length (1000 % 50 == 0)
#define L_SEQ 1000
#define BATCH 1024
#define NBLK (BATCH / NB)   // 128 blocks
#define THREADS 128

typedef unsigned long long ull;

// Preprocessed weights (gate-interleaved): [k=0..51][j=0..63] -> (i,f,g,o)
__device__ float4 g_U4[2 * KH * JP];
__device__ float4 g_W4[JP];   // x weights per j, gates interleaved
__device__ float4 g_B4[JP];   // W_b + U_b per j, gates interleaved
__device__ float  g_L[JP];    // lin_w per j

// ---------- f32x2 helpers (exact packed fp32) ----------
__device__ __forceinline__ ull pk2(float lo, float hi) {
    ull r; asm("mov.b64 %0, {%1, %2};" : "=l"(r) : "f"(lo), "f"(hi)); return r;
}
__device__ __forceinline__ void up2(float& lo, float& hi, ull v) {
    asm("mov.b64 {%0, %1}, %2;" : "=f"(lo), "=f"(hi) : "l"(v));
}
__device__ __forceinline__ ull f2fma(ull a, ull b, ull c) {
    ull d; asm("fma.rn.f32x2 %0, %1, %2, %3;" : "=l"(d) : "l"(a), "l"(b), "l"(c)); return d;
}
__device__ __forceinline__ ull f2add(ull a, ull b) {
    ull d; asm("add.rn.f32x2 %0, %1, %2;" : "=l"(d) : "l"(a), "l"(b)); return d;
}

// ---------- prep: reorder weights into gate-interleaved padded layout ----------
__global__ void prep_kernel(const float* __restrict__ W_w, const float* __restrict__ W_b,
                            const float* __restrict__ U_w, const float* __restrict__ U_b,
                            const float* __restrict__ lin_w) {
    int i = blockIdx.x * 128 + threadIdx.x;   // 0 .. 3327
    int k = i >> 6, j = i & 63;
    float4 u = make_float4(0.f, 0.f, 0.f, 0.f);
    if (k < HIDDEN && j < HIDDEN) {
        u.x = U_w[(0 * HIDDEN + j) * HIDDEN + k];
        u.y = U_w[(1 * HIDDEN + j) * HIDDEN + k];
        u.z = U_w[(2 * HIDDEN + j) * HIDDEN + k];
        u.w = U_w[(3 * HIDDEN + j) * HIDDEN + k];
    }
    g_U4[i] = u;
    if (i < JP) {
        float4 w = make_float4(0.f, 0.f, 0.f, 0.f);
        float4 b = make_float4(0.f, 0.f, 0.f, 0.f);
        float lw = 0.f;
        if (i < HIDDEN) {
            w.x = W_w[0 * HIDDEN + i]; w.y = W_w[1 * HIDDEN + i];
            w.z = W_w[2 * HIDDEN + i]; w.w = W_w[3 * HIDDEN + i];
            b.x = W_b[0 * HIDDEN + i] + U_b[0 * HIDDEN + i];
            b.y = W_b[1 * HIDDEN + i] + U_b[1 * HIDDEN + i];
            b.z = W_b[2 * HIDDEN + i] + U_b[2 * HIDDEN + i];
            b.w = W_b[3 * HIDDEN + i] + U_b[3 * HIDDEN + i];
            lw = lin_w[i];
        }
        g_W4[i] = w; g_B4[i] = b; g_L[i] = lw;
    }
}

// ---------- main recurrent kernel ----------
__global__ void __launch_bounds__(THREADS, 1)
lstm_main(const float* __restrict__ x, const float* __restrict__ lin_b,
          float* __restrict__ out) {
    __shared__ __align__(16) float h_sh[JP][NB];   // [hidden k][batch]
    __shared__ float x_sh[NB][CH];
    __shared__ float4 psum[2][NB][JP];             // partial gates per half
    __shared__ float red_sh[NB];

    const int tid  = threadIdx.x;
    const int half = tid >> 6;      // k-half: 0 -> k 0..25, 1 -> k 26..51
    const int j    = tid & 63;      // hidden unit
    const int lane = tid & 31;
    const int wid  = tid >> 5;
    const int bg0  = blockIdx.x * NB;

    // Register-resident U rows for (half, j): 26 x {(i,f),(g,o)} f32x2
    ull u_if[KH], u_go[KH];
#pragma unroll
    for (int kk = 0; kk < KH; kk++) {
        float4 u = g_U4[(half * KH + kk) * JP + j];
        u_if[kk] = pk2(u.x, u.y);
        u_go[kk] = pk2(u.z, u.w);
    }
    float4 wv = g_W4[j], bv = g_B4[j];
    const ull w_if = pk2(wv.x, wv.y), w_go = pk2(wv.z, wv.w);
    const ull b_if = pk2(bv.x, bv.y), b_go = pk2(bv.z, bv.w);
    const float lw = g_L[j];
    const float lbv = lin_b[0];

    float c[NB];
#pragma unroll
    for (int b = 0; b < NB; b++) c[b] = 0.f;

    for (int i = tid; i < JP * NB; i += THREADS) ((float*)h_sh)[i] = 0.f;
    for (int i = tid; i < NB * CH; i += THREADS) {
        int b = i / CH, tt = i % CH;
        x_sh[b][tt] = x[(bg0 + b) * L_SEQ + tt];
    }
    __syncthreads();

    float outv = 0.f;

    for (int t = 0; t < L_SEQ; ++t) {
        const int tc = t % CH;

        // ---- phase A: partial gates for 8 batches (k-half of the dot) ----
#pragma unroll
        for (int bq = 0; bq < NB; bq += 4) {
            ull a_if[4], a_go[4];
#pragma unroll
            for (int q = 0; q < 4; q++) {
                float xv = x_sh[bq + q][tc];
                ull x2 = pk2(xv, xv);
                ull binit_if = (half == 0) ? f2fma(x2, w_if, b_if) : pk2(0.f, 0.f);
                ull binit_go = (half == 0) ? f2fma(x2, w_go, b_go) : pk2(0.f, 0.f);
                a_if[q] = binit_if;
                a_go[q] = binit_go;
            }
#pragma unroll
            for (int kk = 0; kk < KH; kk++) {
                float4 hq = *(const float4*)&h_sh[half * KH + kk][bq];
                ull h0 = pk2(hq.x, hq.x), h1 = pk2(hq.y, hq.y);
                ull h2 = pk2(hq.z, hq.z), h3 = pk2(hq.w, hq.w);
                a_if[0] = f2fma(h0, u_if[kk], a_if[0]); a_go[0] = f2fma(h0, u_go[kk], a_go[0]);
                a_if[1] = f2fma(h1, u_if[kk], a_if[1]); a_go[1] = f2fma(h1, u_go[kk], a_go[1]);
                a_if[2] = f2fma(h2, u_if[kk], a_if[2]); a_go[2] = f2fma(h2, u_go[kk], a_go[2]);
                a_if[3] = f2fma(h3, u_if[kk], a_if[3]); a_go[3] = f2fma(h3, u_go[kk], a_go[3]);
            }
#pragma unroll
            for (int q = 0; q < 4; q++) {
                ulonglong2 v; v.x = a_if[q]; v.y = a_go[q];
                *(ulonglong2*)&psum[half][bq + q][j] = v;
            }
        }
        __syncthreads();

        // ---- phase B: combine halves, update c/h, reduce output ----
        if (half == 0) {
            float prod[NB], hb[NB];
#pragma unroll
            for (int b = 0; b < NB; b++) {
                ulonglong2 p0 = *(const ulonglong2*)&psum[0][b][j];
                ulonglong2 p1 = *(const ulonglong2*)&psum[1][b][j];
                ull s_if = f2add(p0.x, p1.x);
                ull s_go = f2add(p0.y, p1.y);
                float gi, gf, gg, go;
                up2(gi, gf, s_if);
                up2(gg, go, s_go);
                c[b] = fmaf(gf, c[b], gi * gg);   // f*c + i*g   (no sigmoids!)
                float th = tanhf(c[b]);
                float h = go * th;
                hb[b] = h;
                prod[b] = h * lw;
            }
            *(float4*)&h_sh[j][0] = make_float4(hb[0], hb[1], hb[2], hb[3]);
            *(float4*)&h_sh[j][4] = make_float4(hb[4], hb[5], hb[6], hb[7]);

#pragma unroll
            for (int off = 16; off >= 1; off >>= 1) {
#pragma unroll
                for (int b = 0; b < NB; b++)
                    prod[b] += __shfl_xor_sync(0xffffffffu, prod[b], off);
            }
            if (lane < NB) {
                float v = prod[0];
#pragma unroll
                for (int b = 1; b < NB; b++) v = (lane == b) ? prod[b] : v;
                if (wid == 1) red_sh[lane] = v;
                else outv = v;
            }
        } else {
            // half-1 warps: prefetch next x chunk while half-0 updates state
            if (tc == CH - 1 && t + 1 < L_SEQ) {
                int t0 = t + 1;
                for (int i = tid - 64; i < NB * CH; i += 64) {
                    int b = i / CH, tt = i % CH;
                    x_sh[b][tt] = x[(bg0 + b) * L_SEQ + t0 + tt];
                }
            }
        }
        __syncthreads();

        if (wid == 0 && lane < NB)
            out[(bg0 + lane) * L_SEQ + t] = outv + red_sh[lane] + lbv;
    }
}

extern "C" void kernel_launch(void* const* d_in, const int* in_sizes, int n_in,
                              void* d_out, int out_size) {
    (void)in_sizes; (void)n_in; (void)out_size;
    const float* x     = (const float*)d_in[0];
    const float* W_w   = (const float*)d_in[1];
    const float* W_b   = (const float*)d_in[2];
    const float* U_w   = (const float*)d_in[3];
    const float* U_b   = (const float*)d_in[4];
    const float* lin_w = (const float*)d_in[5];
    const float* lin_b = (const float*)d_in[6];
    // d_in[7] = future (static 0) — ignored.

    prep_kernel<<<26, 128>>>(W_w, W_b, U_w, U_b, lin_w);
    lstm_main<<<NBLK, THREADS>>>(x, lin_b, (float*)d_out);
}

// round 2
// speedup vs baseline: 1.3294x; 1.3294x over previous
#include <cuda_runtime.h>

#define HIDDEN 51
#define JP 64          // padded hidden units (threads per k-half)
#define KH 26          // k-iterations per half (2*26 = 52 = 51 + 1 zero pad)
#define KROWS 52
#define NBG 4          // batch rows per group
#define L_SEQ 1000
#define BATCH 1024
#define NBLK 128       // 128 CTAs x 8 batches (2 groups of 4)
#define THREADS 256

typedef unsigned long long ull;

// Preprocessed weights (gate-interleaved): [k=0..51][j=0..63] -> (i,f,g,o)
__device__ float4 g_U4[KROWS * JP];
__device__ float4 g_W4[JP];   // x weights per j, gates interleaved
__device__ float4 g_B4[JP];   // W_b + U_b per j, gates interleaved
__device__ float  g_L[JP];    // lin_w per j

// ---------- f32x2 helpers (exact packed fp32) ----------
__device__ __forceinline__ ull pk2(float lo, float hi) {
    ull r; asm("mov.b64 %0, {%1, %2};" : "=l"(r) : "f"(lo), "f"(hi)); return r;
}
__device__ __forceinline__ void up2(float& lo, float& hi, ull v) {
    asm("mov.b64 {%0, %1}, %2;" : "=f"(lo), "=f"(hi) : "l"(v));
}
__device__ __forceinline__ ull f2fma(ull a, ull b, ull c) {
    ull d; asm("fma.rn.f32x2 %0, %1, %2, %3;" : "=l"(d) : "l"(a), "l"(b), "l"(c)); return d;
}
__device__ __forceinline__ ull f2add(ull a, ull b) {
    ull d; asm("add.rn.f32x2 %0, %1, %2;" : "=l"(d) : "l"(a), "l"(b)); return d;
}

// fast accurate tanh: 1 - 2/(exp(2x)+1) via ex2.approx + rcp.approx (~1e-7 abs err)
// Saturates correctly: x>>0 -> e=inf -> rcp=0 -> 1;  x<<0 -> e=0 -> 1-2 = -1.
__device__ __forceinline__ float fast_tanh(float xv) {
    float e;
    asm("ex2.approx.f32 %0, %1;" : "=f"(e) : "f"(xv * 2.8853900817779268f));
    float r;
    asm("rcp.approx.f32 %0, %1;" : "=f"(r) : "f"(e + 1.0f));
    return fmaf(-2.0f, r, 1.0f);
}

__device__ __forceinline__ void group_bar(int barid) {
    asm volatile("bar.sync %0, %1;" :: "r"(barid), "r"(128) : "memory");
}

// ---------- prep: reorder weights into gate-interleaved padded layout ----------
__global__ void prep_kernel(const float* __restrict__ W_w, const float* __restrict__ W_b,
                            const float* __restrict__ U_w, const float* __restrict__ U_b,
                            const float* __restrict__ lin_w) {
    int i = blockIdx.x * 128 + threadIdx.x;   // 0 .. 3327
    int k = i >> 6, j = i & 63;
    float4 u = make_float4(0.f, 0.f, 0.f, 0.f);
    if (k < HIDDEN && j < HIDDEN) {
        u.x = U_w[(0 * HIDDEN + j) * HIDDEN + k];
        u.y = U_w[(1 * HIDDEN + j) * HIDDEN + k];
        u.z = U_w[(2 * HIDDEN + j) * HIDDEN + k];
        u.w = U_w[(3 * HIDDEN + j) * HIDDEN + k];
    }
    g_U4[i] = u;
    if (i < JP) {
        float4 w = make_float4(0.f, 0.f, 0.f, 0.f);
        float4 b = make_float4(0.f, 0.f, 0.f, 0.f);
        float lw = 0.f;
        if (i < HIDDEN) {
            w.x = W_w[0 * HIDDEN + i]; w.y = W_w[1 * HIDDEN + i];
            w.z = W_w[2 * HIDDEN + i]; w.w = W_w[3 * HIDDEN + i];
            b.x = W_b[0 * HIDDEN + i] + U_b[0 * HIDDEN + i];
            b.y = W_b[1 * HIDDEN + i] + U_b[1 * HIDDEN + i];
            b.z = W_b[2 * HIDDEN + i] + U_b[2 * HIDDEN + i];
            b.w = W_b[3 * HIDDEN + i] + U_b[3 * HIDDEN + i];
            lw = lin_w[i];
        }
        g_W4[i] = w; g_B4[i] = b; g_L[i] = lw;
    }
}

// ---------- main recurrent kernel ----------
// 256 threads = 2 INDEPENDENT groups of 128 (own batches, own named barrier).
// Within a group: half = k-half (0: k 0..25, 1: k 26..51), j = hidden unit.
__global__ void __launch_bounds__(THREADS, 1)
lstm_main(const float* __restrict__ x, const float* __restrict__ lin_b,
          float* __restrict__ out) {
    __shared__ __align__(16) float  h_sh[2][JP][NBG];        // [group][unit][batch]
    __shared__ __align__(16) float4 psum[2][2][NBG][JP];     // [group][half][batch][j]
    __shared__ float redp[2][4][2];                          // [group][warp-in-grp][slot]

    const int tid   = threadIdx.x;
    const int g     = tid >> 7;        // group 0/1
    const int gtid  = tid & 127;
    const int half  = gtid >> 6;       // k-half
    const int j     = gtid & 63;       // hidden unit
    const int lane  = tid & 31;
    const int wg    = gtid >> 5;       // warp within group 0..3
    const int barid = g + 1;           // named barrier per group
    const int b0    = blockIdx.x * (2 * NBG) + g * NBG;

    // Register-resident U rows for (half, j): 26 x {(i,f),(g,o)} f32x2
    ull u_if[KH], u_go[KH];
#pragma unroll
    for (int kk = 0; kk < KH; kk++) {
        float4 u = g_U4[(half * KH + kk) * JP + j];
        u_if[kk] = pk2(u.x, u.y);
        u_go[kk] = pk2(u.z, u.w);
    }
    float4 wv = g_W4[j], bv = g_B4[j];
    const ull w_if = pk2(wv.x, wv.y), w_go = pk2(wv.z, wv.w);
    const ull b_if = pk2(bv.x, bv.y), b_go = pk2(bv.z, bv.w);
    const float lw  = g_L[j];
    const float lbv = lin_b[0];

    // This thread's cell state: 2 batches (half 0 -> b 0,1; half 1 -> b 2,3)
    float c[2] = {0.f, 0.f};

    // zero h
    for (int i = gtid; i < JP * NBG; i += 128) ((float*)h_sh[g])[i] = 0.f;

    // preload x for t=0
    float xn[NBG];
#pragma unroll
    for (int q = 0; q < NBG; q++) xn[q] = x[(b0 + q) * L_SEQ + 0];

    __syncthreads();

    for (int t = 0; t < L_SEQ; ++t) {
        // ---- phase A: partial gates for 4 batches (this thread's k-half) ----
        ull a_if[NBG], a_go[NBG];
#pragma unroll
        for (int q = 0; q < NBG; q++) {
            ull x2 = pk2(xn[q], xn[q]);
            a_if[q] = (half == 0) ? f2fma(x2, w_if, b_if) : pk2(0.f, 0.f);
            a_go[q] = (half == 0) ? f2fma(x2, w_go, b_go) : pk2(0.f, 0.f);
        }
#pragma unroll
        for (int kk = 0; kk < KH; kk++) {
            float4 hq = *(const float4*)&h_sh[g][half * KH + kk][0];
            ull h0 = pk2(hq.x, hq.x), h1 = pk2(hq.y, hq.y);
            ull h2 = pk2(hq.z, hq.z), h3 = pk2(hq.w, hq.w);
            a_if[0] = f2fma(h0, u_if[kk], a_if[0]); a_go[0] = f2fma(h0, u_go[kk], a_go[0]);
            a_if[1] = f2fma(h1, u_if[kk], a_if[1]); a_go[1] = f2fma(h1, u_go[kk], a_go[1]);
            a_if[2] = f2fma(h2, u_if[kk], a_if[2]); a_go[2] = f2fma(h2, u_go[kk], a_go[2]);
            a_if[3] = f2fma(h3, u_if[kk], a_if[3]); a_go[3] = f2fma(h3, u_go[kk], a_go[3]);
        }
#pragma unroll
        for (int q = 0; q < NBG; q++) {
            ulonglong2 v; v.x = a_if[q]; v.y = a_go[q];
            *(ulonglong2*)&psum[g][half][q][j] = v;
        }

        group_bar(barid);

        // ---- prefetch next x (latency hidden under phase B) ----
        {
            int tn = (t + 1 < L_SEQ) ? t + 1 : t;
#pragma unroll
            for (int q = 0; q < NBG; q++) xn[q] = x[(b0 + q) * L_SEQ + tn];
        }

        // ---- phase B: combine halves, update c/h for THIS thread's 2 batches ----
        float prod[2];
#pragma unroll
        for (int s = 0; s < 2; s++) {
            int b = half * 2 + s;
            ulonglong2 p0 = *(const ulonglong2*)&psum[g][0][b][j];
            ulonglong2 p1 = *(const ulonglong2*)&psum[g][1][b][j];
            ull s_if = f2add(p0.x, p1.x);
            ull s_go = f2add(p0.y, p1.y);
            float gi, gf, gg, go;
            up2(gi, gf, s_if);
            up2(gg, go, s_go);
            c[s] = fmaf(gf, c[s], gi * gg);     // f*c + i*g (no sigmoids!)
            float h = go * fast_tanh(c[s]);
            h_sh[g][j][b] = h;
            prod[s] = h * lw;
        }
        // reduce over j within warp (j spans 2 warps per half)
#pragma unroll
        for (int off = 16; off >= 1; off >>= 1) {
            prod[0] += __shfl_xor_sync(0xffffffffu, prod[0], off);
            prod[1] += __shfl_xor_sync(0xffffffffu, prod[1], off);
        }
        if (lane == 0) { redp[g][wg][0] = prod[0]; redp[g][wg][1] = prod[1]; }

        group_bar(barid);

        // ---- output: 4 threads per group finish the reduction & store ----
        if (gtid < NBG) {
            int b = gtid;
            int wbase = (b >> 1) << 1;   // batches 0,1 from warps 0,1; 2,3 from 2,3
            float v = redp[g][wbase][b & 1] + redp[g][wbase + 1][b & 1] + lbv;
            out[(b0 + b) * L_SEQ + t] = v;
        }
    }
}

extern "C" void kernel_launch(void* const* d_in, const int* in_sizes, int n_in,
                              void* d_out, int out_size) {
    (void)in_sizes; (void)n_in; (void)out_size;
    const float* x     = (const float*)d_in[0];
    const float* W_w   = (const float*)d_in[1];
    const float* W_b   = (const float*)d_in[2];
    const float* U_w   = (const float*)d_in[3];
    const float* U_b   = (const float*)d_in[4];
    const float* lin_w = (const float*)d_in[5];
    const float* lin_b = (const float*)d_in[6];
    // d_in[7] = future (static 0) — ignored.

    prep_kernel<<<26, 128>>>(W_w, W_b, U_w, U_b, lin_w);
    lstm_main<<<NBLK, THREADS>>>(x, lin_b, (float*)d_out);
}